// round 1
// baseline (speedup 1.0000x reference)
#include <cuda_runtime.h>

// Z rows. Per row:
//   out[0:48]  = (1/sqrt(48)) * x2[0]   * (x1 . w00[:,w])    w00: 48x48 row-major (u fastest over rows)
//   out[48+w*3+j] = (1/sqrt(48)) * x2[1+j] * (x1 . w01[:,w]) w01: 48x10
// weights row layout: [w00 (2304 floats)][w01 (480 floats)] = 2784 floats/row.

#define NS 48
#define NV 10
#define WPR 2784           // weights per row
#define OPR 78             // outputs per row
#define NORM 0.14433756729740643f   // 1/sqrt(48) == NORM_0E == NORM_1O

#define ROWS_PER_BLOCK 4
#define THREADS_PER_ROW 64

__global__ __launch_bounds__(ROWS_PER_BLOCK * THREADS_PER_ROW)
void tpfirst_kernel(const float* __restrict__ x1,
                    const float* __restrict__ x2,
                    const float* __restrict__ W,
                    float* __restrict__ out,
                    int Z)
{
    const int group = threadIdx.x >> 6;        // 0..3, row within block
    const int lane  = threadIdx.x & 63;        // 0..63, thread within row
    const int z     = blockIdx.x * ROWS_PER_BLOCK + group;

    __shared__ float x1s[ROWS_PER_BLOCK][NS];
    __shared__ float x2s[ROWS_PER_BLOCK][4];

    if (z < Z) {
        if (lane < NS)
            x1s[group][lane] = x1[(size_t)z * NS + lane];
        else if (lane < NS + 4)
            x2s[group][lane - NS] = x2[(size_t)z * 9 + (lane - NS)];
    }
    __syncthreads();

    if (z >= Z) return;

    const float* __restrict__ w = W + (size_t)z * WPR;
    float*       __restrict__ o = out + (size_t)z * OPR;
    const float* xr = x1s[group];

    if (lane < NS) {
        // 0e part: column `lane` of w00 (stride NS). Consecutive lanes ->
        // consecutive addresses -> fully coalesced streaming of the 9216B block.
        float s = 0.f;
        #pragma unroll
        for (int u = 0; u < NS; u++)
            s = fmaf(xr[u], w[u * NS + lane], s);
        o[lane] = NORM * x2s[group][0] * s;
    } else if (lane < NS + NV) {
        // 1o part: column (lane-48) of w01 (stride NV).
        const int wc = lane - NS;
        const float* __restrict__ w01 = w + NS * NS;
        float t = 0.f;
        #pragma unroll
        for (int u = 0; u < NS; u++)
            t = fmaf(xr[u], w01[u * NV + wc], t);
        t *= NORM;
        o[NS + wc * 3 + 0] = t * x2s[group][1];
        o[NS + wc * 3 + 1] = t * x2s[group][2];
        o[NS + wc * 3 + 2] = t * x2s[group][3];
    }
}

extern "C" void kernel_launch(void* const* d_in, const int* in_sizes, int n_in,
                              void* d_out, int out_size)
{
    const float* x1 = (const float*)d_in[0];
    const float* x2 = (const float*)d_in[1];
    const float* W  = (const float*)d_in[2];
    float* out = (float*)d_out;

    const int Z = in_sizes[0] / NS;
    const int blocks = (Z + ROWS_PER_BLOCK - 1) / ROWS_PER_BLOCK;
    tpfirst_kernel<<<blocks, ROWS_PER_BLOCK * THREADS_PER_ROW>>>(x1, x2, W, out, Z);
}

// round 3
// speedup vs baseline: 1.0779x; 1.0779x over previous
#include <cuda_runtime.h>

// Per row z (Z=200000):
//   out[0:48]        = NORM * x2[z,0]   * (x1[z,:] @ w00)   w00 = weights[z, :2304] as 48x48
//   out[48+6p .. ]   = NORM * x2[z,1+j] * (x1[z,:] @ w01)   w01 = weights[z, 2304:] as 48x10
// NORM = 1/sqrt(48) for both terms.
//
// Role A blocks: w00 via float4 loads (12 quad-threads/row, 20 rows/block).
// Role B blocks: w01 via float2 loads (5 pair-threads/row, 48 rows/block).
// No warp mixes roles -> zero divergence; all weight traffic is LDG.128/LDG.64.

#define NS   48
#define NV   10
#define WPR  2784
#define OPR  78
#define NORM 0.14433756729740643f

#define TPB    240
#define ROWS_A 20      // 20 rows * 12 quads  = 240 threads
#define ROWS_B 48      // 48 rows * 5 pairs   = 240 threads

__global__ __launch_bounds__(TPB)
void tpfirst_kernel(const float* __restrict__ x1,
                    const float* __restrict__ x2,
                    const float* __restrict__ W,
                    float* __restrict__ out,
                    int Z, int ablocks)
{
    __shared__ float x1s[ROWS_B * NS];   // 2304 floats, covers both roles
    __shared__ float x2s[ROWS_B * 3];

    const int t = threadIdx.x;

    if (blockIdx.x < ablocks) {
        // ================= role A : w00 (48x48), float4 =================
        const int z0 = blockIdx.x * ROWS_A;

        for (int i = t; i < ROWS_A * NS; i += TPB) {
            int zz = z0 + i / NS;
            x1s[i] = (zz < Z) ? x1[(size_t)zz * NS + (i % NS)] : 0.f;
        }
        if (t < ROWS_A) {
            int zz = z0 + t;
            x2s[t] = (zz < Z) ? x2[(size_t)zz * 9] : 0.f;
        }
        __syncthreads();

        const int r = t / 12;          // row within block
        const int q = t % 12;          // column quad: cols 4q..4q+3
        const int z = z0 + r;
        if (z >= Z) return;

        const float4* __restrict__ w4 =
            (const float4*)W + (size_t)z * (WPR / 4) + q;
        const float* xr = x1s + r * NS;

        float s0 = 0.f, s1 = 0.f, s2 = 0.f, s3 = 0.f;
        #pragma unroll
        for (int u = 0; u < NS; u++) {
            float4 w = w4[u * (NS / 4)];
            float  xv = xr[u];
            s0 = fmaf(xv, w.x, s0);
            s1 = fmaf(xv, w.y, s1);
            s2 = fmaf(xv, w.z, s2);
            s3 = fmaf(xv, w.w, s3);
        }
        const float c = NORM * x2s[r];
        float2* o2 = (float2*)(out + (size_t)z * OPR + 4 * q);  // even offset -> 8B aligned
        o2[0] = make_float2(c * s0, c * s1);
        o2[1] = make_float2(c * s2, c * s3);
    } else {
        // ================= role B : w01 (48x10), float2 =================
        const int z0 = (blockIdx.x - ablocks) * ROWS_B;

        for (int i = t; i < ROWS_B * NS; i += TPB) {
            int zz = z0 + i / NS;
            x1s[i] = (zz < Z) ? x1[(size_t)zz * NS + (i % NS)] : 0.f;
        }
        for (int i = t; i < ROWS_B * 3; i += TPB) {
            int zz = z0 + i / 3;
            x2s[i] = (zz < Z) ? x2[(size_t)zz * 9 + 1 + (i % 3)] : 0.f;
        }
        __syncthreads();

        const int r = t / 5;           // row within block
        const int p = t % 5;           // column pair: cols 2p, 2p+1
        const int z = z0 + r;
        if (z >= Z) return;

        const float2* __restrict__ w2 =
            (const float2*)W + (size_t)z * (WPR / 2) + (NS * NS / 2) + p;
        const float* xr = x1s + r * NS;

        float s0 = 0.f, s1 = 0.f;
        #pragma unroll
        for (int u = 0; u < NS; u++) {
            float2 w = w2[u * (NV / 2)];
            float  xv = xr[u];
            s0 = fmaf(xv, w.x, s0);
            s1 = fmaf(xv, w.y, s1);
        }
        s0 *= NORM;
        s1 *= NORM;
        const float a = x2s[r * 3 + 0];
        const float b = x2s[r * 3 + 1];
        const float c = x2s[r * 3 + 2];
        float* o = out + (size_t)z * OPR + NS + 6 * p;
        o[0] = s0 * a; o[1] = s0 * b; o[2] = s0 * c;
        o[3] = s1 * a; o[4] = s1 * b; o[5] = s1 * c;
    }
}

extern "C" void kernel_launch(void* const* d_in, const int* in_sizes, int n_in,
                              void* d_out, int out_size)
{
    const float* x1 = (const float*)d_in[0];
    const float* x2 = (const float*)d_in[1];
    const float* W  = (const float*)d_in[2];
    float* out = (float*)d_out;

    const int Z = in_sizes[0] / NS;
    const int ablocks = (Z + ROWS_A - 1) / ROWS_A;
    const int bblocks = (Z + ROWS_B - 1) / ROWS_B;
    tpfirst_kernel<<<ablocks + bblocks, TPB>>>(x1, x2, W, out, Z, ablocks);
}

// round 4
// speedup vs baseline: 1.1471x; 1.0642x over previous
#include <cuda_runtime.h>

// Per row z (Z=200000):
//   out[0:48]         = NORM * x2[z,0]   * (x1[z,:] @ w00)   w00 = weights[z,:2304] as 48x48
//   out[48+6p+...]    = NORM * x2[z,1+j] * (x1[z,:] @ w01)   w01 = weights[z,2304:] as 48x10
// NORM = 1/sqrt(48).
//
// Fused block: 16 rows/block, 288 threads.
//   warps 0-5  (t in [0,192)) : w00, float4 loads, 12 quad-threads/row
//   t in [192,272)            : w01, float2 loads, 5 pair-threads/row
//   t in [272,288)            : idle after cooperative smem load
// No warp mixes roles. Each block streams one contiguous 16*11136B weight
// region and writes complete 312B output rows.

#define NS   48
#define NV   10
#define WPR  2784
#define OPR  78
#define NORM 0.14433756729740643f

#define RPB  16         // rows per block
#define TPB  288        // 9 warps

__global__ __launch_bounds__(TPB)
void tpfirst_kernel(const float* __restrict__ x1,
                    const float* __restrict__ x2,
                    const float* __restrict__ W,
                    float* __restrict__ out,
                    int Z)
{
    __shared__ float x1s[RPB * NS];     // 768 floats
    __shared__ float x2s[RPB * 4];      // x2[z,0..3]

    const int t  = threadIdx.x;
    const int z0 = blockIdx.x * RPB;

    // cooperative staging (all 288 threads)
    #pragma unroll
    for (int i = t; i < RPB * NS; i += TPB) {
        int zz = z0 + i / NS;
        x1s[i] = (zz < Z) ? x1[(size_t)zz * NS + (i % NS)] : 0.f;
    }
    if (t < RPB * 4) {
        int zz = z0 + (t >> 2);
        x2s[t] = (zz < Z) ? x2[(size_t)zz * 9 + (t & 3)] : 0.f;
    }
    __syncthreads();

    if (t < 192) {
        // ---------------- w00: float4, 12 quads/row ----------------
        const int r = t / 12;
        const int q = t % 12;
        const int z = z0 + r;
        if (z >= Z) return;

        const float4* __restrict__ w4 =
            (const float4*)W + (size_t)z * (WPR / 4) + q;
        const float* xr = x1s + r * NS;

        float s0 = 0.f, s1 = 0.f, s2 = 0.f, s3 = 0.f;
        #pragma unroll
        for (int u = 0; u < NS; u++) {
            float4 w  = w4[u * (NS / 4)];
            float  xv = xr[u];
            s0 = fmaf(xv, w.x, s0);
            s1 = fmaf(xv, w.y, s1);
            s2 = fmaf(xv, w.z, s2);
            s3 = fmaf(xv, w.w, s3);
        }
        const float c = NORM * x2s[r * 4 + 0];
        float2* o2 = (float2*)(out + (size_t)z * OPR + 4 * q);
        o2[0] = make_float2(c * s0, c * s1);
        o2[1] = make_float2(c * s2, c * s3);
    } else if (t < 192 + RPB * 5) {
        // ---------------- w01: float2, 5 pairs/row ----------------
        const int u5 = t - 192;
        const int r  = u5 / 5;
        const int p  = u5 % 5;
        const int z  = z0 + r;
        if (z >= Z) return;

        const float2* __restrict__ w2 =
            (const float2*)W + (size_t)z * (WPR / 2) + (NS * NS / 2) + p;
        const float* xr = x1s + r * NS;

        float s0 = 0.f, s1 = 0.f;
        #pragma unroll
        for (int u = 0; u < NS; u++) {
            float2 w  = w2[u * (NV / 2)];
            float  xv = xr[u];
            s0 = fmaf(xv, w.x, s0);
            s1 = fmaf(xv, w.y, s1);
        }
        s0 *= NORM;
        s1 *= NORM;
        const float a = x2s[r * 4 + 1];
        const float b = x2s[r * 4 + 2];
        const float c = x2s[r * 4 + 3];
        float2* o2 = (float2*)(out + (size_t)z * OPR + NS + 6 * p);
        o2[0] = make_float2(s0 * a, s0 * b);
        o2[1] = make_float2(s0 * c, s1 * a);
        o2[2] = make_float2(s1 * b, s1 * c);
    }
}

extern "C" void kernel_launch(void* const* d_in, const int* in_sizes, int n_in,
                              void* d_out, int out_size)
{
    const float* x1 = (const float*)d_in[0];
    const float* x2 = (const float*)d_in[1];
    const float* W  = (const float*)d_in[2];
    float* out = (float*)d_out;

    const int Z = in_sizes[0] / NS;
    const int blocks = (Z + RPB - 1) / RPB;
    tpfirst_kernel<<<blocks, TPB>>>(x1, x2, W, out, Z);
}